// round 3
// baseline (speedup 1.0000x reference)
#include <cuda_runtime.h>

#define BATCH   2
#define NSEQ    2048
#define DMODEL  2048
#define INNERD  2048
#define EQKV    6144
#define NHEADS  16
#define HDIM    128
#define WINDOW  512
#define N_TOK   (BATCH * NSEQ)   // 4096

typedef unsigned long long ull;

// Scratch (allocation-free contract: __device__ globals)
__device__ float g_qkv[N_TOK * EQKV];   // ~100 MB
__device__ float g_att[N_TOK * INNERD]; // ~33 MB

// ---------------- f32x2 helpers (Blackwell packed fp32 pipe) ----------------
__device__ __forceinline__ ull f2dup(float x) {
    ull r; asm("mov.b64 %0, {%1, %1};" : "=l"(r) : "f"(x)); return r;
}
__device__ __forceinline__ void ffma2(ull &d, ull a, ull b) {
    asm("fma.rn.f32x2 %0, %1, %2, %0;" : "+l"(d) : "l"(a), "l"(b));
}
__device__ __forceinline__ void fmul2(ull &d, ull a) {
    asm("mul.rn.f32x2 %0, %0, %1;" : "+l"(d) : "l"(a));
}
__device__ __forceinline__ float hadd2(ull a) {
    return __uint_as_float((unsigned)a) + __uint_as_float((unsigned)(a >> 32));
}
__device__ __forceinline__ float lo2(ull a) { return __uint_as_float((unsigned)a); }
__device__ __forceinline__ float hi2(ull a) { return __uint_as_float((unsigned)(a >> 32)); }

// ---------------- NT SGEMM: C[M,N] = A[M,K] * B[N,K]^T ----------------
// grid = (N/128, M/128), 256 threads, 8x8 per thread, BK=16.
__global__ __launch_bounds__(256, 2) void gemm_nt(
    const float* __restrict__ A, const float* __restrict__ B,
    float* __restrict__ C, int N, int K)
{
    __shared__ float As[16][132];
    __shared__ float Bs[16][132];

    int tid = threadIdx.x;
    int tx  = tid & 15;
    int ty  = tid >> 4;
    int r   = tid >> 2;          // 0..63
    int kq  = (tid & 3) << 2;    // 0,4,8,12

    long arow = (long)blockIdx.y * 128;
    long bcol = (long)blockIdx.x * 128;

    const float* Ap = A + (arow + r) * (long)K + kq;
    const float* Bp = B + (bcol + r) * (long)K + kq;

    float4 ra0 = *(const float4*)(Ap);
    float4 ra1 = *(const float4*)(Ap + 64L * K);
    float4 rb0 = *(const float4*)(Bp);
    float4 rb1 = *(const float4*)(Bp + 64L * K);

    ull acc[8][4];
    #pragma unroll
    for (int i = 0; i < 8; i++)
        #pragma unroll
        for (int j = 0; j < 4; j++) acc[i][j] = 0ULL;

    for (int kk = 0; kk < K; kk += 16) {
        As[kq + 0][r]      = ra0.x; As[kq + 1][r]      = ra0.y;
        As[kq + 2][r]      = ra0.z; As[kq + 3][r]      = ra0.w;
        As[kq + 0][r + 64] = ra1.x; As[kq + 1][r + 64] = ra1.y;
        As[kq + 2][r + 64] = ra1.z; As[kq + 3][r + 64] = ra1.w;
        Bs[kq + 0][r]      = rb0.x; Bs[kq + 1][r]      = rb0.y;
        Bs[kq + 2][r]      = rb0.z; Bs[kq + 3][r]      = rb0.w;
        Bs[kq + 0][r + 64] = rb1.x; Bs[kq + 1][r + 64] = rb1.y;
        Bs[kq + 2][r + 64] = rb1.z; Bs[kq + 3][r + 64] = rb1.w;
        __syncthreads();

        if (kk + 16 < K) {  // prefetch next K-tile into registers
            ra0 = *(const float4*)(Ap + kk + 16);
            ra1 = *(const float4*)(Ap + 64L * K + kk + 16);
            rb0 = *(const float4*)(Bp + kk + 16);
            rb1 = *(const float4*)(Bp + 64L * K + kk + 16);
        }

        #pragma unroll
        for (int k = 0; k < 16; k++) {
            float4 a0 = *(const float4*)&As[k][ty * 8];
            float4 a1 = *(const float4*)&As[k][ty * 8 + 4];
            const ull* bp2 = (const ull*)&Bs[k][tx * 8];
            ull b0 = bp2[0], b1 = bp2[1], b2 = bp2[2], b3 = bp2[3];
            ull ad[8];
            ad[0] = f2dup(a0.x); ad[1] = f2dup(a0.y);
            ad[2] = f2dup(a0.z); ad[3] = f2dup(a0.w);
            ad[4] = f2dup(a1.x); ad[5] = f2dup(a1.y);
            ad[6] = f2dup(a1.z); ad[7] = f2dup(a1.w);
            #pragma unroll
            for (int i = 0; i < 8; i++) {
                ffma2(acc[i][0], ad[i], b0);
                ffma2(acc[i][1], ad[i], b1);
                ffma2(acc[i][2], ad[i], b2);
                ffma2(acc[i][3], ad[i], b3);
            }
        }
        __syncthreads();
    }

    float* Cp = C + (arow + ty * 8) * (long)N + bcol + tx * 8;
    #pragma unroll
    for (int i = 0; i < 8; i++) {
        float4 c0, c1;
        c0.x = lo2(acc[i][0]); c0.y = hi2(acc[i][0]);
        c0.z = lo2(acc[i][1]); c0.w = hi2(acc[i][1]);
        c1.x = lo2(acc[i][2]); c1.y = hi2(acc[i][2]);
        c1.z = lo2(acc[i][3]); c1.w = hi2(acc[i][3]);
        *(float4*)(Cp + (long)i * N)     = c0;
        *(float4*)(Cp + (long)i * N + 4) = c1;
    }
}

// ---------------- RoPE (GPT-NeoX half-split), in-place on q,k of g_qkv ------
// thread per (token m, pair d); loops over heads.
__global__ void rope_kernel() {
    int idx = blockIdx.x * blockDim.x + threadIdx.x;
    if (idx >= N_TOK * 64) return;
    int d = idx & 63;
    int m = idx >> 6;           // b*NSEQ + n
    int n = m & (NSEQ - 1);

    // angle in double, then range-reduce, then fp32 trig (err ~1e-7 rad)
    double inv = exp(-(double)d * (9.210340371976184 / 64.0)); // ln(1e4)/64
    double ang = (double)n * inv;
    const double TWO_PI = 6.283185307179586476925286766559;
    double w = ang - floor(ang / TWO_PI) * TWO_PI;
    float c = cosf((float)w);
    float s = sinf((float)w);

    float* base = g_qkv + (long)m * EQKV + d;
    #pragma unroll
    for (int h = 0; h < NHEADS; h++) {
        float* q = base + h * HDIM;
        float q1 = q[0], q2 = q[64];
        q[0]  = q1 * c - q2 * s;
        q[64] = q2 * c + q1 * s;
        float* k = q + INNERD;
        float k1 = k[0], k2 = k[64];
        k[0]  = k1 * c - k2 * s;
        k[64] = k2 * c + k1 * s;
    }
}

// ---------------- Windowed flash attention ----------------
// CTA = (64 queries, head, batch). 256 threads: tx=tid&15 (keys/dims),
// ty=tid>>4 (query rows, strided: rows {ty, ty+16, ty+32, ty+48}).
#define ATTN_SMEM_BYTES (3 * 64 * 132 * 4 + 64 * 76 * 4)

__global__ __launch_bounds__(256, 1) void attn_kernel() {
    extern __shared__ float sm[];
    float* sQ = sm;                  // [64][132]  row-major [i][d]
    float* sK = sm + 64 * 132;       // [64][132]  [j][d]
    float* sV = sm + 2 * 64 * 132;   // [64][132]  [j][d]
    float* sP = sm + 3 * 64 * 132;   // [64][76]   [i][j]

    int tid = threadIdx.x;
    int tx  = tid & 15;
    int ty  = tid >> 4;
    int qb  = blockIdx.x;
    int h   = blockIdx.y;
    int b   = blockIdx.z;
    int qs  = qb * 64;

    const float scale = 0.088388347648318447f;   // 1/sqrt(128)
    const float* qg = g_qkv + (long)(b * NSEQ + qs) * EQKV + h * HDIM;

    // load Q tile (pre-scaled)
    #pragma unroll
    for (int it = 0; it < 8; it++) {
        int e  = tid + it * 256;
        int rr = e >> 5;
        int c4 = (e & 31) << 2;
        float4 v = *(const float4*)(qg + (long)rr * EQKV + c4);
        v.x *= scale; v.y *= scale; v.z *= scale; v.w *= scale;
        *(float4*)&sQ[rr * 132 + c4] = v;
    }

    float mrow[4], lrow[4];
    ull oacc[4][4];
    #pragma unroll
    for (int i = 0; i < 4; i++) {
        mrow[i] = -1e30f; lrow[i] = 0.f;
        #pragma unroll
        for (int j = 0; j < 4; j++) oacc[i][j] = 0ULL;
    }

    int kt0 = (qs >= WINDOW) ? ((qs - WINDOW + 1) >> 6) : 0;
    int kt1 = qb;

    for (int kt = kt0; kt <= kt1; kt++) {
        int ks = kt << 6;
        __syncthreads();   // previous phase-2 must finish before K/V overwrite
        const float* kg = g_qkv + (long)(b * NSEQ + ks) * EQKV + INNERD + h * HDIM;
        const float* vg = kg + INNERD;
        #pragma unroll
        for (int it = 0; it < 8; it++) {
            int e  = tid + it * 256;
            int rr = e >> 5;
            int c4 = (e & 31) << 2;
            *(float4*)&sK[rr * 132 + c4] = *(const float4*)(kg + (long)rr * EQKV + c4);
            *(float4*)&sV[rr * 132 + c4] = *(const float4*)(vg + (long)rr * EQKV + c4);
        }
        __syncthreads();

        // ---- S = Q K^T (f32x2 packed over d-pairs, no pack movs needed) ----
        ull sacc[4][4];
        #pragma unroll
        for (int i = 0; i < 4; i++)
            #pragma unroll
            for (int j = 0; j < 4; j++) sacc[i][j] = 0ULL;

        #pragma unroll 8
        for (int d0 = 0; d0 < 128; d0 += 4) {
            ulonglong2 qv[4], kv[4];
            #pragma unroll
            for (int i = 0; i < 4; i++)
                qv[i] = *(const ulonglong2*)&sQ[(ty + 16 * i) * 132 + d0];
            #pragma unroll
            for (int j = 0; j < 4; j++)
                kv[j] = *(const ulonglong2*)&sK[(tx + 16 * j) * 132 + d0];
            #pragma unroll
            for (int i = 0; i < 4; i++)
                #pragma unroll
                for (int j = 0; j < 4; j++) {
                    ffma2(sacc[i][j], qv[i].x, kv[j].x);
                    ffma2(sacc[i][j], qv[i].y, kv[j].y);
                }
        }

        float s[4][4];
        #pragma unroll
        for (int i = 0; i < 4; i++)
            #pragma unroll
            for (int j = 0; j < 4; j++) s[i][j] = hadd2(sacc[i][j]);

        // ---- sliding-window causal mask ----
        #pragma unroll
        for (int i = 0; i < 4; i++) {
            int qi = qs + ty + 16 * i;
            #pragma unroll
            for (int j = 0; j < 4; j++) {
                int kj = ks + tx + 16 * j;
                if (kj > qi || kj <= qi - WINDOW) s[i][j] = -1e30f;
            }
        }

        // ---- online softmax (row reduce over the 16 tx lanes) ----
        #pragma unroll
        for (int i = 0; i < 4; i++) {
            float mx = fmaxf(fmaxf(s[i][0], s[i][1]), fmaxf(s[i][2], s[i][3]));
            #pragma unroll
            for (int o = 1; o < 16; o <<= 1)
                mx = fmaxf(mx, __shfl_xor_sync(0xffffffffu, mx, o));
            float mnew  = fmaxf(mrow[i], mx);
            float alpha = __expf(mrow[i] - mnew);
            mrow[i] = mnew;

            float p[4], rs = 0.f;
            #pragma unroll
            for (int j = 0; j < 4; j++) {
                p[j] = (s[i][j] < -1e29f) ? 0.f : __expf(s[i][j] - mnew);
                rs += p[j];
            }
            #pragma unroll
            for (int o = 1; o < 16; o <<= 1)
                rs += __shfl_xor_sync(0xffffffffu, rs, o);
            lrow[i] = lrow[i] * alpha + rs;

            ull a2 = f2dup(alpha);
            #pragma unroll
            for (int j = 0; j < 4; j++) fmul2(oacc[i][j], a2);
            #pragma unroll
            for (int j = 0; j < 4; j++)
                sP[(ty + 16 * i) * 76 + tx + 16 * j] = p[j];
        }
        __syncthreads();

        // ---- O += P V (f32x2 packed over d-pairs) ----
        #pragma unroll 8
        for (int j = 0; j < 64; j++) {
            const ull* vp = (const ull*)&sV[j * 132 + tx * 8];
            ull v0 = vp[0], v1 = vp[1], v2 = vp[2], v3 = vp[3];
            #pragma unroll
            for (int i = 0; i < 4; i++) {
                ull pd = f2dup(sP[(ty + 16 * i) * 76 + j]);
                ffma2(oacc[i][0], pd, v0);
                ffma2(oacc[i][1], pd, v1);
                ffma2(oacc[i][2], pd, v2);
                ffma2(oacc[i][3], pd, v3);
            }
        }
    }

    // ---- normalize + write [m][h*128 + d] ----
    #pragma unroll
    for (int i = 0; i < 4; i++) {
        float inv = 1.0f / lrow[i];
        float4 c0, c1;
        c0.x = lo2(oacc[i][0]) * inv; c0.y = hi2(oacc[i][0]) * inv;
        c0.z = lo2(oacc[i][1]) * inv; c0.w = hi2(oacc[i][1]) * inv;
        c1.x = lo2(oacc[i][2]) * inv; c1.y = hi2(oacc[i][2]) * inv;
        c1.z = lo2(oacc[i][3]) * inv; c1.w = hi2(oacc[i][3]) * inv;
        float* op = g_att + (long)(b * NSEQ + qs + ty + 16 * i) * INNERD
                  + h * HDIM + tx * 8;
        *(float4*)op       = c0;
        *(float4*)(op + 4) = c1;
    }
}

// ---------------- launch ----------------
extern "C" void kernel_launch(void* const* d_in, const int* in_sizes, int n_in,
                              void* d_out, int out_size) {
    const float* x     = (const float*)d_in[0];
    const float* w_qkv = (const float*)d_in[1];
    const float* w_o   = (const float*)d_in[2];
    float* y = (float*)d_out;

    float *qkv = nullptr, *att = nullptr;
    cudaGetSymbolAddress((void**)&qkv, g_qkv);
    cudaGetSymbolAddress((void**)&att, g_att);

    cudaFuncSetAttribute(attn_kernel,
                         cudaFuncAttributeMaxDynamicSharedMemorySize,
                         ATTN_SMEM_BYTES);

    // 1) QKV projection: [4096,2048] x [6144,2048]^T -> [4096,6144]
    gemm_nt<<<dim3(EQKV / 128, N_TOK / 128), 256>>>(x, w_qkv, qkv, EQKV, DMODEL);
    // 2) RoPE in place on q,k
    rope_kernel<<<(N_TOK * 64) / 256, 256>>>();
    // 3) windowed attention -> g_att [4096, 2048]
    attn_kernel<<<dim3(NSEQ / 64, NHEADS, BATCH), 256, ATTN_SMEM_BYTES>>>();
    // 4) output projection: [4096,2048] x [2048,2048]^T -> y
    gemm_nt<<<dim3(DMODEL / 128, N_TOK / 128), 256>>>(att, w_o, y, DMODEL, INNERD);
}

// round 5
// speedup vs baseline: 1.5284x; 1.5284x over previous
#include <cuda_runtime.h>
#include <cuda_bf16.h>
#include <cstdint>

#define BATCH   2
#define NSEQ    2048
#define DMODEL  2048
#define INNERD  2048
#define EQKV    6144
#define NHEADS  16
#define HDIM    128
#define WINDOW  512
#define N_TOK   (BATCH * NSEQ)   // 4096

typedef unsigned long long ull;
typedef __nv_bfloat16 bf16;

// ---------------- scratch (__device__ globals: allocation-free contract) ----
__device__ float g_qkv[N_TOK * EQKV];   // fp32 qkv (attention consumes this)
__device__ float g_att[N_TOK * INNERD]; // fp32 attention output
__device__ __align__(16) bf16 g_xh[N_TOK * DMODEL];
__device__ __align__(16) bf16 g_xl[N_TOK * DMODEL];
__device__ __align__(16) bf16 g_wqh[EQKV * DMODEL];
__device__ __align__(16) bf16 g_wql[EQKV * DMODEL];
__device__ __align__(16) bf16 g_woh[DMODEL * INNERD];
__device__ __align__(16) bf16 g_wol[DMODEL * INNERD];
__device__ __align__(16) bf16 g_ah[N_TOK * INNERD];
__device__ __align__(16) bf16 g_al[N_TOK * INNERD];

// ---------------- PTX helpers (baseline ISA only: no 'a' features) ----------
__device__ __forceinline__ uint32_t smem_u32(const void* p) {
    uint32_t a;
    asm("{ .reg .u64 t; cvta.to.shared.u64 t, %1; cvt.u32.u64 %0, t; }"
        : "=r"(a) : "l"(p));
    return a;
}
__device__ __forceinline__ void cp16(uint32_t dst, const void* src) {
    asm volatile("cp.async.cg.shared.global [%0], [%1], 16;" :: "r"(dst), "l"(src));
}
__device__ __forceinline__ void cp_commit() {
    asm volatile("cp.async.commit_group;" ::: "memory");
}
__device__ __forceinline__ void ldsm_x4(uint32_t* r, uint32_t addr) {
    asm volatile("ldmatrix.sync.aligned.m8n8.x4.shared.b16 {%0,%1,%2,%3}, [%4];"
                 : "=r"(r[0]), "=r"(r[1]), "=r"(r[2]), "=r"(r[3]) : "r"(addr));
}
__device__ __forceinline__ void ldsm_x2(uint32_t* r, uint32_t addr) {
    asm volatile("ldmatrix.sync.aligned.m8n8.x2.shared.b16 {%0,%1}, [%2];"
                 : "=r"(r[0]), "=r"(r[1]) : "r"(addr));
}
__device__ __forceinline__ void mma16816(float* c, const uint32_t* a, const uint32_t* b) {
    asm volatile("mma.sync.aligned.m16n8k16.row.col.f32.bf16.bf16.f32 "
                 "{%0,%1,%2,%3}, {%4,%5,%6,%7}, {%8,%9}, {%0,%1,%2,%3};"
                 : "+f"(c[0]), "+f"(c[1]), "+f"(c[2]), "+f"(c[3])
                 : "r"(a[0]), "r"(a[1]), "r"(a[2]), "r"(a[3]),
                   "r"(b[0]), "r"(b[1]));
}

// ---------------- f32x2 helpers (for attention) ----------------
__device__ __forceinline__ ull f2dup(float x) {
    ull r; asm("mov.b64 %0, {%1, %1};" : "=l"(r) : "f"(x)); return r;
}
__device__ __forceinline__ void ffma2(ull &d, ull a, ull b) {
    asm("fma.rn.f32x2 %0, %1, %2, %0;" : "+l"(d) : "l"(a), "l"(b));
}
__device__ __forceinline__ void fmul2(ull &d, ull a) {
    asm("mul.rn.f32x2 %0, %0, %1;" : "+l"(d) : "l"(a));
}
__device__ __forceinline__ float hadd2(ull a) {
    return __uint_as_float((unsigned)a) + __uint_as_float((unsigned)(a >> 32));
}
__device__ __forceinline__ float lo2(ull a) { return __uint_as_float((unsigned)a); }
__device__ __forceinline__ float hi2(ull a) { return __uint_as_float((unsigned)(a >> 32)); }

// ---------------- fp32 -> bf16 hi/lo split ----------------
__global__ void split_bf16(const float4* __restrict__ in,
                           __nv_bfloat162* __restrict__ hi,
                           __nv_bfloat162* __restrict__ lo, int n4) {
    int i = blockIdx.x * blockDim.x + threadIdx.x;
    if (i >= n4) return;
    float4 v = in[i];
    bf16 h0 = __float2bfloat16(v.x);
    bf16 h1 = __float2bfloat16(v.y);
    bf16 h2 = __float2bfloat16(v.z);
    bf16 h3 = __float2bfloat16(v.w);
    bf16 l0 = __float2bfloat16(v.x - __bfloat162float(h0));
    bf16 l1 = __float2bfloat16(v.y - __bfloat162float(h1));
    bf16 l2 = __float2bfloat16(v.z - __bfloat162float(h2));
    bf16 l3 = __float2bfloat16(v.w - __bfloat162float(h3));
    hi[i * 2]     = __halves2bfloat162(h0, h1);
    hi[i * 2 + 1] = __halves2bfloat162(h2, h3);
    lo[i * 2]     = __halves2bfloat162(l0, l1);
    lo[i * 2 + 1] = __halves2bfloat162(l2, l3);
}

// ---------------- mma.sync split-bf16 NT GEMM ----------------
// C[M,N] = A[M,K] * B[N,K]^T in fp32, A,B given as bf16 hi/lo pairs.
// CTA: 128x128 tile, BK=32, 256 threads (8 warps = 2m x 4n), 64x32 per warp.
// Per k16 step: C += Ah*Bh + Ah*Bl + Al*Bh  (fp32 accum in registers).
//
// SMEM stage layout (32 KB):
//   A at +0:     [hl][kc][row 0..127][16 bf16]   (hl*8192 + kc*4096 + row*32)
//   B at +16384: same with 128 n-rows
#define GEMM_STAGE  32768
#define GEMM_SMEM_BYTES (2 * GEMM_STAGE)

__device__ __forceinline__ void load_stage(
    uint32_t st, const bf16* __restrict__ Ah, const bf16* __restrict__ Al,
    const bf16* __restrict__ Bh, const bf16* __restrict__ Bl,
    long tm, long tn, int k0, int K, int tid)
{
    #pragma unroll
    for (int it = 0; it < 8; it++) {
        int s   = tid + it * 256;       // 0..2047
        int mat = s >> 10;              // 0=A, 1=B
        int hl  = (s >> 9) & 1;
        int r   = (s >> 2) & 127;
        int q   = s & 3;                // 16B quad within 64B k-row
        const bf16* src;
        long row;
        if (mat == 0) { src = hl ? Al : Ah; row = tm + r; }
        else          { src = hl ? Bl : Bh; row = tn + r; }
        uint32_t dst = st + mat * 16384 + hl * 8192 + (q >> 1) * 4096
                     + r * 32 + (q & 1) * 16;
        cp16(dst, src + row * (long)K + k0 + q * 8);
    }
    cp_commit();
}

__global__ __launch_bounds__(256, 1) void gemm_tc(
    const bf16* __restrict__ Ah, const bf16* __restrict__ Al,
    const bf16* __restrict__ Bh, const bf16* __restrict__ Bl,
    float* __restrict__ C, int Nn, int K)
{
    extern __shared__ char dynsmem[];
    uint32_t st0 = smem_u32(dynsmem);

    int tid  = threadIdx.x;
    int lane = tid & 31;
    int wid  = tid >> 5;
    int wm   = (wid >> 2) * 64;     // warp m offset (0 or 64)
    int wn   = (wid & 3) * 32;      // warp n offset (0,32,64,96)

    long tm = (long)blockIdx.y * 128;
    long tn = (long)blockIdx.x * 128;
    int NC = K / 32;

    // per-lane ldmatrix address offsets
    uint32_t aOff = (uint32_t)((wm + (lane & 15)) * 32 + (lane >> 4) * 16);
    uint32_t bOff = (uint32_t)((wn + (lane & 7)) * 32 + ((lane >> 3) & 1) * 16);

    float acc[4][4][4];
    #pragma unroll
    for (int mi = 0; mi < 4; mi++)
        #pragma unroll
        for (int ni = 0; ni < 4; ni++)
            #pragma unroll
            for (int q = 0; q < 4; q++) acc[mi][ni][q] = 0.f;

    load_stage(st0, Ah, Al, Bh, Bl, tm, tn, 0, K, tid);

    for (int c = 0; c < NC; c++) {
        if (c + 1 < NC) {
            load_stage(st0 + ((c + 1) & 1) * GEMM_STAGE,
                       Ah, Al, Bh, Bl, tm, tn, (c + 1) * 32, K, tid);
            asm volatile("cp.async.wait_group 1;" ::: "memory");
        } else {
            asm volatile("cp.async.wait_group 0;" ::: "memory");
        }
        __syncthreads();

        uint32_t sa = st0 + (c & 1) * GEMM_STAGE;
        uint32_t sb = sa + 16384;

        #pragma unroll
        for (int kc = 0; kc < 2; kc++) {
            uint32_t ab = sa + kc * 4096 + aOff;
            uint32_t bb = sb + kc * 4096 + bOff;

            uint32_t aH[4][4], aL[4][4], bH[4][2], bL[4][2];
            #pragma unroll
            for (int mi = 0; mi < 4; mi++) {
                ldsm_x4(aH[mi], ab + mi * 512);
                ldsm_x4(aL[mi], ab + 8192 + mi * 512);
            }
            #pragma unroll
            for (int ni = 0; ni < 4; ni++) {
                ldsm_x2(bH[ni], bb + ni * 256);
                ldsm_x2(bL[ni], bb + 8192 + ni * 256);
            }
            #pragma unroll
            for (int mi = 0; mi < 4; mi++)
                #pragma unroll
                for (int ni = 0; ni < 4; ni++) {
                    mma16816(acc[mi][ni], aH[mi], bH[ni]);
                    mma16816(acc[mi][ni], aH[mi], bL[ni]);
                    mma16816(acc[mi][ni], aL[mi], bH[ni]);
                }
        }
        __syncthreads();
    }

    // epilogue: fragment -> gmem (float2 stores)
    int r0 = (lane >> 2);
    int c0 = (lane & 3) * 2;
    #pragma unroll
    for (int mi = 0; mi < 4; mi++) {
        long row = tm + wm + mi * 16 + r0;
        #pragma unroll
        for (int ni = 0; ni < 4; ni++) {
            long col = tn + wn + ni * 8 + c0;
            *(float2*)&C[row * (long)Nn + col] =
                make_float2(acc[mi][ni][0], acc[mi][ni][1]);
            *(float2*)&C[(row + 8) * (long)Nn + col] =
                make_float2(acc[mi][ni][2], acc[mi][ni][3]);
        }
    }
}

// ---------------- RoPE (GPT-NeoX half-split), in-place on q,k of g_qkv ------
__global__ void rope_kernel() {
    int idx = blockIdx.x * blockDim.x + threadIdx.x;
    if (idx >= N_TOK * 64) return;
    int d = idx & 63;
    int m = idx >> 6;
    int n = m & (NSEQ - 1);

    double inv = exp(-(double)d * (9.210340371976184 / 64.0));
    double ang = (double)n * inv;
    const double TWO_PI = 6.283185307179586476925286766559;
    double w = ang - floor(ang / TWO_PI) * TWO_PI;
    float c = cosf((float)w);
    float s = sinf((float)w);

    float* base = g_qkv + (long)m * EQKV + d;
    #pragma unroll
    for (int h = 0; h < NHEADS; h++) {
        float* q = base + h * HDIM;
        float q1 = q[0], q2 = q[64];
        q[0]  = q1 * c - q2 * s;
        q[64] = q2 * c + q1 * s;
        float* k = q + INNERD;
        float k1 = k[0], k2 = k[64];
        k[0]  = k1 * c - k2 * s;
        k[64] = k2 * c + k1 * s;
    }
}

// ---------------- Windowed flash attention (fp32, f32x2 packed) -------------
#define ATTN_SMEM_BYTES (3 * 64 * 132 * 4 + 64 * 76 * 4)

__global__ __launch_bounds__(256, 1) void attn_kernel() {
    extern __shared__ float sm[];
    float* sQ = sm;
    float* sK = sm + 64 * 132;
    float* sV = sm + 2 * 64 * 132;
    float* sP = sm + 3 * 64 * 132;

    int tid = threadIdx.x;
    int tx  = tid & 15;
    int ty  = tid >> 4;
    int qb  = blockIdx.x;
    int h   = blockIdx.y;
    int b   = blockIdx.z;
    int qs  = qb * 64;

    const float scale = 0.088388347648318447f;
    const float* qg = g_qkv + (long)(b * NSEQ + qs) * EQKV + h * HDIM;

    #pragma unroll
    for (int it = 0; it < 8; it++) {
        int e  = tid + it * 256;
        int rr = e >> 5;
        int c4 = (e & 31) << 2;
        float4 v = *(const float4*)(qg + (long)rr * EQKV + c4);
        v.x *= scale; v.y *= scale; v.z *= scale; v.w *= scale;
        *(float4*)&sQ[rr * 132 + c4] = v;
    }

    float mrow[4], lrow[4];
    ull oacc[4][4];
    #pragma unroll
    for (int i = 0; i < 4; i++) {
        mrow[i] = -1e30f; lrow[i] = 0.f;
        #pragma unroll
        for (int j = 0; j < 4; j++) oacc[i][j] = 0ULL;
    }

    int kt0 = (qs >= WINDOW) ? ((qs - WINDOW + 1) >> 6) : 0;
    int kt1 = qb;

    for (int kt = kt0; kt <= kt1; kt++) {
        int ks = kt << 6;
        __syncthreads();
        const float* kg = g_qkv + (long)(b * NSEQ + ks) * EQKV + INNERD + h * HDIM;
        const float* vg = kg + INNERD;
        #pragma unroll
        for (int it = 0; it < 8; it++) {
            int e  = tid + it * 256;
            int rr = e >> 5;
            int c4 = (e & 31) << 2;
            *(float4*)&sK[rr * 132 + c4] = *(const float4*)(kg + (long)rr * EQKV + c4);
            *(float4*)&sV[rr * 132 + c4] = *(const float4*)(vg + (long)rr * EQKV + c4);
        }
        __syncthreads();

        ull sacc[4][4];
        #pragma unroll
        for (int i = 0; i < 4; i++)
            #pragma unroll
            for (int j = 0; j < 4; j++) sacc[i][j] = 0ULL;

        #pragma unroll 8
        for (int d0 = 0; d0 < 128; d0 += 4) {
            ulonglong2 qv[4], kv[4];
            #pragma unroll
            for (int i = 0; i < 4; i++)
                qv[i] = *(const ulonglong2*)&sQ[(ty + 16 * i) * 132 + d0];
            #pragma unroll
            for (int j = 0; j < 4; j++)
                kv[j] = *(const ulonglong2*)&sK[(tx + 16 * j) * 132 + d0];
            #pragma unroll
            for (int i = 0; i < 4; i++)
                #pragma unroll
                for (int j = 0; j < 4; j++) {
                    ffma2(sacc[i][j], qv[i].x, kv[j].x);
                    ffma2(sacc[i][j], qv[i].y, kv[j].y);
                }
        }

        float s[4][4];
        #pragma unroll
        for (int i = 0; i < 4; i++)
            #pragma unroll
            for (int j = 0; j < 4; j++) s[i][j] = hadd2(sacc[i][j]);

        #pragma unroll
        for (int i = 0; i < 4; i++) {
            int qi = qs + ty + 16 * i;
            #pragma unroll
            for (int j = 0; j < 4; j++) {
                int kj = ks + tx + 16 * j;
                if (kj > qi || kj <= qi - WINDOW) s[i][j] = -1e30f;
            }
        }

        #pragma unroll
        for (int i = 0; i < 4; i++) {
            float mx = fmaxf(fmaxf(s[i][0], s[i][1]), fmaxf(s[i][2], s[i][3]));
            #pragma unroll
            for (int o = 1; o < 16; o <<= 1)
                mx = fmaxf(mx, __shfl_xor_sync(0xffffffffu, mx, o));
            float mnew  = fmaxf(mrow[i], mx);
            float alpha = __expf(mrow[i] - mnew);
            mrow[i] = mnew;

            float p[4], rs = 0.f;
            #pragma unroll
            for (int j = 0; j < 4; j++) {
                p[j] = (s[i][j] < -1e29f) ? 0.f : __expf(s[i][j] - mnew);
                rs += p[j];
            }
            #pragma unroll
            for (int o = 1; o < 16; o <<= 1)
                rs += __shfl_xor_sync(0xffffffffu, rs, o);
            lrow[i] = lrow[i] * alpha + rs;

            ull a2 = f2dup(alpha);
            #pragma unroll
            for (int j = 0; j < 4; j++) fmul2(oacc[i][j], a2);
            #pragma unroll
            for (int j = 0; j < 4; j++)
                sP[(ty + 16 * i) * 76 + tx + 16 * j] = p[j];
        }
        __syncthreads();

        #pragma unroll 8
        for (int j = 0; j < 64; j++) {
            const ull* vp = (const ull*)&sV[j * 132 + tx * 8];
            ull v0 = vp[0], v1 = vp[1], v2 = vp[2], v3 = vp[3];
            #pragma unroll
            for (int i = 0; i < 4; i++) {
                ull pd = f2dup(sP[(ty + 16 * i) * 76 + j]);
                ffma2(oacc[i][0], pd, v0);
                ffma2(oacc[i][1], pd, v1);
                ffma2(oacc[i][2], pd, v2);
                ffma2(oacc[i][3], pd, v3);
            }
        }
    }

    #pragma unroll
    for (int i = 0; i < 4; i++) {
        float inv = 1.0f / lrow[i];
        float4 c0, c1;
        c0.x = lo2(oacc[i][0]) * inv; c0.y = hi2(oacc[i][0]) * inv;
        c0.z = lo2(oacc[i][1]) * inv; c0.w = hi2(oacc[i][1]) * inv;
        c1.x = lo2(oacc[i][2]) * inv; c1.y = hi2(oacc[i][2]) * inv;
        c1.z = lo2(oacc[i][3]) * inv; c1.w = hi2(oacc[i][3]) * inv;
        float* op = g_att + (long)(b * NSEQ + qs + ty + 16 * i) * INNERD
                  + h * HDIM + tx * 8;
        *(float4*)op       = c0;
        *(float4*)(op + 4) = c1;
    }
}

// ---------------- launch ----------------
extern "C" void kernel_launch(void* const* d_in, const int* in_sizes, int n_in,
                              void* d_out, int out_size) {
    const float* x     = (const float*)d_in[0];
    const float* w_qkv = (const float*)d_in[1];
    const float* w_o   = (const float*)d_in[2];
    float* y = (float*)d_out;

    float *qkv = nullptr, *att = nullptr;
    bf16 *xh, *xl, *wqh, *wql, *woh, *wol, *ah, *al;
    cudaGetSymbolAddress((void**)&qkv, g_qkv);
    cudaGetSymbolAddress((void**)&att, g_att);
    cudaGetSymbolAddress((void**)&xh,  g_xh);
    cudaGetSymbolAddress((void**)&xl,  g_xl);
    cudaGetSymbolAddress((void**)&wqh, g_wqh);
    cudaGetSymbolAddress((void**)&wql, g_wql);
    cudaGetSymbolAddress((void**)&woh, g_woh);
    cudaGetSymbolAddress((void**)&wol, g_wol);
    cudaGetSymbolAddress((void**)&ah,  g_ah);
    cudaGetSymbolAddress((void**)&al,  g_al);

    cudaFuncSetAttribute(gemm_tc,
                         cudaFuncAttributeMaxDynamicSharedMemorySize,
                         GEMM_SMEM_BYTES);
    cudaFuncSetAttribute(attn_kernel,
                         cudaFuncAttributeMaxDynamicSharedMemorySize,
                         ATTN_SMEM_BYTES);

    // 1) split inputs to bf16 hi/lo
    {
        int n4 = (N_TOK * DMODEL) / 4;
        split_bf16<<<n4 / 256, 256>>>((const float4*)x,
                                      (__nv_bfloat162*)xh, (__nv_bfloat162*)xl, n4);
    }
    {
        int n4 = (EQKV * DMODEL) / 4;
        split_bf16<<<n4 / 256, 256>>>((const float4*)w_qkv,
                                      (__nv_bfloat162*)wqh, (__nv_bfloat162*)wql, n4);
    }
    {
        int n4 = (DMODEL * INNERD) / 4;
        split_bf16<<<n4 / 256, 256>>>((const float4*)w_o,
                                      (__nv_bfloat162*)woh, (__nv_bfloat162*)wol, n4);
    }

    // 2) QKV projection: [4096,2048] x [6144,2048]^T -> g_qkv [4096,6144]
    gemm_tc<<<dim3(EQKV / 128, N_TOK / 128), 256, GEMM_SMEM_BYTES>>>(
        xh, xl, wqh, wql, qkv, EQKV, DMODEL);

    // 3) RoPE in place on q,k
    rope_kernel<<<(N_TOK * 64) / 256, 256>>>();

    // 4) windowed attention -> g_att [4096, 2048]
    attn_kernel<<<dim3(NSEQ / 64, NHEADS, BATCH), 256, ATTN_SMEM_BYTES>>>();

    // 5) split attention output
    {
        int n4 = (N_TOK * INNERD) / 4;
        split_bf16<<<n4 / 256, 256>>>((const float4*)att,
                                      (__nv_bfloat162*)ah, (__nv_bfloat162*)al, n4);
    }

    // 6) output projection: [4096,2048] x [2048,2048]^T -> y
    gemm_tc<<<dim3(DMODEL / 128, N_TOK / 128), 256, GEMM_SMEM_BYTES>>>(
        ah, al, woh, wol, y, DMODEL, INNERD);
}

// round 7
// speedup vs baseline: 2.2102x; 1.4460x over previous
#include <cuda_runtime.h>
#include <cuda_fp16.h>
#include <cstdint>

#define BATCH   2
#define NSEQ    2048
#define DMODEL  2048
#define INNERD  2048
#define EQKV    6144
#define NHEADS  16
#define HDIM    128
#define WINDOW  512
#define N_TOK   (BATCH * NSEQ)   // 4096

typedef unsigned long long ull;

// ---------------- scratch (__device__ globals: allocation-free contract) ----
__device__ float g_qkv[N_TOK * EQKV];   // fp32 qkv (attention consumes this)
__device__ float g_att[N_TOK * INNERD]; // fp32 attention output
__device__ __align__(16) __half g_xh[N_TOK * DMODEL];   // x hi
__device__ __align__(16) __half g_xl[N_TOK * DMODEL];   // x lo (residual)
__device__ __align__(16) __half g_wq[EQKV * DMODEL];    // w_qkv rounded
__device__ __align__(16) __half g_wo[DMODEL * INNERD];  // w_o rounded
__device__ __align__(16) __half g_ah[N_TOK * INNERD];   // att hi
__device__ __align__(16) __half g_al[N_TOK * INNERD];   // att lo

// ---------------- PTX helpers (baseline ISA only) ----------------
__device__ __forceinline__ uint32_t smem_u32(const void* p) {
    uint32_t a;
    asm("{ .reg .u64 t; cvta.to.shared.u64 t, %1; cvt.u32.u64 %0, t; }"
        : "=r"(a) : "l"(p));
    return a;
}
__device__ __forceinline__ void cp16(uint32_t dst, const void* src) {
    asm volatile("cp.async.cg.shared.global [%0], [%1], 16;" :: "r"(dst), "l"(src));
}
__device__ __forceinline__ void cp_commit() {
    asm volatile("cp.async.commit_group;" ::: "memory");
}
__device__ __forceinline__ void ldsm_x4(uint32_t* r, uint32_t addr) {
    asm volatile("ldmatrix.sync.aligned.m8n8.x4.shared.b16 {%0,%1,%2,%3}, [%4];"
                 : "=r"(r[0]), "=r"(r[1]), "=r"(r[2]), "=r"(r[3]) : "r"(addr));
}
__device__ __forceinline__ void ldsm_x2(uint32_t* r, uint32_t addr) {
    asm volatile("ldmatrix.sync.aligned.m8n8.x2.shared.b16 {%0,%1}, [%2];"
                 : "=r"(r[0]), "=r"(r[1]) : "r"(addr));
}
__device__ __forceinline__ void mma16816(float* c, const uint32_t* a, const uint32_t* b) {
    asm volatile("mma.sync.aligned.m16n8k16.row.col.f32.f16.f16.f32 "
                 "{%0,%1,%2,%3}, {%4,%5,%6,%7}, {%8,%9}, {%0,%1,%2,%3};"
                 : "+f"(c[0]), "+f"(c[1]), "+f"(c[2]), "+f"(c[3])
                 : "r"(a[0]), "r"(a[1]), "r"(a[2]), "r"(a[3]),
                   "r"(b[0]), "r"(b[1]));
}

// ---------------- f32x2 helpers (for attention) ----------------
__device__ __forceinline__ ull f2dup(float x) {
    ull r; asm("mov.b64 %0, {%1, %1};" : "=l"(r) : "f"(x)); return r;
}
__device__ __forceinline__ void ffma2(ull &d, ull a, ull b) {
    asm("fma.rn.f32x2 %0, %1, %2, %0;" : "+l"(d) : "l"(a), "l"(b));
}
__device__ __forceinline__ void fmul2(ull &d, ull a) {
    asm("mul.rn.f32x2 %0, %0, %1;" : "+l"(d) : "l"(a));
}
__device__ __forceinline__ float hadd2(ull a) {
    return __uint_as_float((unsigned)a) + __uint_as_float((unsigned)(a >> 32));
}
__device__ __forceinline__ float lo2(ull a) { return __uint_as_float((unsigned)a); }
__device__ __forceinline__ float hi2(ull a) { return __uint_as_float((unsigned)(a >> 32)); }

// ---------------- fp32 -> fp16 hi/lo split (activations) ----------------
__global__ void split_f16(const float4* __restrict__ in,
                          __half2* __restrict__ hi,
                          __half2* __restrict__ lo, int n4) {
    int i = blockIdx.x * blockDim.x + threadIdx.x;
    if (i >= n4) return;
    float4 v = in[i];
    __half h0 = __float2half_rn(v.x);
    __half h1 = __float2half_rn(v.y);
    __half h2 = __float2half_rn(v.z);
    __half h3 = __float2half_rn(v.w);
    __half l0 = __float2half_rn(v.x - __half2float(h0));
    __half l1 = __float2half_rn(v.y - __half2float(h1));
    __half l2 = __float2half_rn(v.z - __half2float(h2));
    __half l3 = __float2half_rn(v.w - __half2float(h3));
    hi[i * 2]     = __halves2half2(h0, h1);
    hi[i * 2 + 1] = __halves2half2(h2, h3);
    lo[i * 2]     = __halves2half2(l0, l1);
    lo[i * 2 + 1] = __halves2half2(l2, l3);
}

// ---------------- fp32 -> fp16 round (weights) ----------------
__global__ void conv_f16(const float4* __restrict__ in,
                         __half2* __restrict__ out, int n4) {
    int i = blockIdx.x * blockDim.x + threadIdx.x;
    if (i >= n4) return;
    float4 v = in[i];
    out[i * 2]     = __halves2half2(__float2half_rn(v.x), __float2half_rn(v.y));
    out[i * 2 + 1] = __halves2half2(__float2half_rn(v.z), __float2half_rn(v.w));
}

// ---------------- mma.sync split-fp16 NT GEMM ----------------
// C[M,N] = (Ah + Al)[M,K] * B[N,K]^T in fp32 (B already fp16-rounded).
// CTA: 128x128 tile, BK=32, 256 threads (8 warps = 2m x 4n), 64x32 per warp.
// 2 MMAs per (mi,ni,k16): acc += Ah*B; acc += Al*B.
//
// SMEM stage layout (24 KB):
//   A at +0:     [hl][kc][row 0..127][32B]  (hl*8192 + kc*4096 + row*32)
//   B at +16384: [kc][row 0..127][32B]      (kc*4096 + row*32)
#define GEMM_STAGE   24576
#define GEMM_NSTAGE  3
#define GEMM_SMEM_BYTES (GEMM_NSTAGE * GEMM_STAGE)   // 73728

__device__ __forceinline__ void load_stage_body(
    uint32_t st, const __half* __restrict__ Ah, const __half* __restrict__ Al,
    const __half* __restrict__ Bw, long tm, long tn, int k0, int K, int tid)
{
    #pragma unroll
    for (int it = 0; it < 6; it++) {
        int s = tid + it * 256;          // 0..1535
        uint32_t dst; const __half* src; long row;
        if (s < 1024) {                  // A hi/lo
            int hl = s >> 9;
            int r  = (s >> 2) & 127;
            int q  = s & 3;
            src = hl ? Al : Ah; row = tm + r;
            dst = st + hl * 8192 + (q >> 1) * 4096 + r * 32 + (q & 1) * 16;
            cp16(dst, src + row * (long)K + k0 + q * 8);
        } else {                         // B
            int s2 = s - 1024;
            int r  = (s2 >> 2) & 127;
            int q  = s2 & 3;
            row = tn + r;
            dst = st + 16384 + (q >> 1) * 4096 + r * 32 + (q & 1) * 16;
            cp16(dst, Bw + row * (long)K + k0 + q * 8);
        }
    }
}

__global__ __launch_bounds__(256, 2) void gemm_tc(
    const __half* __restrict__ Ah, const __half* __restrict__ Al,
    const __half* __restrict__ Bw,
    float* __restrict__ C, int Nn, int K)
{
    extern __shared__ char dynsmem[];
    uint32_t st0 = smem_u32(dynsmem);

    int tid  = threadIdx.x;
    int lane = tid & 31;
    int wid  = tid >> 5;
    int wm   = (wid >> 2) * 64;     // warp m offset (0 or 64)
    int wn   = (wid & 3) * 32;      // warp n offset (0,32,64,96)

    long tm = (long)blockIdx.y * 128;
    long tn = (long)blockIdx.x * 128;
    int NC = K / 32;

    uint32_t aOff = (uint32_t)((wm + (lane & 15)) * 32 + (lane >> 4) * 16);
    uint32_t bOff = (uint32_t)((wn + (lane & 7)) * 32 + ((lane >> 3) & 1) * 16);

    float acc[4][4][4];
    #pragma unroll
    for (int mi = 0; mi < 4; mi++)
        #pragma unroll
        for (int ni = 0; ni < 4; ni++)
            #pragma unroll
            for (int q = 0; q < 4; q++) acc[mi][ni][q] = 0.f;

    // prologue: stages 0 and 1 in flight
    load_stage_body(st0, Ah, Al, Bw, tm, tn, 0, K, tid);
    cp_commit();
    if (NC > 1) load_stage_body(st0 + GEMM_STAGE, Ah, Al, Bw, tm, tn, 32, K, tid);
    cp_commit();

    int stg = 0;          // stage index of chunk c
    int stg2 = 2;         // stage index of chunk c+2
    for (int c = 0; c < NC; c++) {
        asm volatile("cp.async.wait_group 1;" ::: "memory");
        __syncthreads();

        // issue loads for chunk c+2 into the stage freed at iter c-1
        if (c + 2 < NC)
            load_stage_body(st0 + stg2 * GEMM_STAGE, Ah, Al, Bw,
                            tm, tn, (c + 2) * 32, K, tid);
        cp_commit();      // always commit (empty group ok) to keep counts uniform

        uint32_t sa = st0 + stg * GEMM_STAGE;
        uint32_t sb = sa + 16384;

        #pragma unroll
        for (int kc = 0; kc < 2; kc++) {
            uint32_t ab = sa + kc * 4096 + aOff;
            uint32_t bb = sb + kc * 4096 + bOff;

            uint32_t aH[4][4], aL[4][4], bH[4][2];
            #pragma unroll
            for (int mi = 0; mi < 4; mi++) {
                ldsm_x4(aH[mi], ab + mi * 512);
                ldsm_x4(aL[mi], ab + 8192 + mi * 512);
            }
            #pragma unroll
            for (int ni = 0; ni < 4; ni++)
                ldsm_x2(bH[ni], bb + ni * 256);

            #pragma unroll
            for (int mi = 0; mi < 4; mi++)
                #pragma unroll
                for (int ni = 0; ni < 4; ni++) {
                    mma16816(acc[mi][ni], aH[mi], bH[ni]);
                    mma16816(acc[mi][ni], aL[mi], bH[ni]);
                }
        }

        stg  = (stg  + 1 == GEMM_NSTAGE) ? 0 : stg + 1;
        stg2 = (stg2 + 1 == GEMM_NSTAGE) ? 0 : stg2 + 1;
    }

    // epilogue: fragment -> gmem (float2 stores)
    int r0 = (lane >> 2);
    int c0 = (lane & 3) * 2;
    #pragma unroll
    for (int mi = 0; mi < 4; mi++) {
        long row = tm + wm + mi * 16 + r0;
        #pragma unroll
        for (int ni = 0; ni < 4; ni++) {
            long col = tn + wn + ni * 8 + c0;
            *(float2*)&C[row * (long)Nn + col] =
                make_float2(acc[mi][ni][0], acc[mi][ni][1]);
            *(float2*)&C[(row + 8) * (long)Nn + col] =
                make_float2(acc[mi][ni][2], acc[mi][ni][3]);
        }
    }
}

// ---------------- RoPE (GPT-NeoX half-split), in-place on q,k of g_qkv ------
__global__ void rope_kernel() {
    int idx = blockIdx.x * blockDim.x + threadIdx.x;
    if (idx >= N_TOK * 64) return;
    int d = idx & 63;
    int m = idx >> 6;
    int n = m & (NSEQ - 1);

    double inv = exp(-(double)d * (9.210340371976184 / 64.0));
    double ang = (double)n * inv;
    const double TWO_PI = 6.283185307179586476925286766559;
    double w = ang - floor(ang / TWO_PI) * TWO_PI;
    float c = cosf((float)w);
    float s = sinf((float)w);

    float* base = g_qkv + (long)m * EQKV + d;
    #pragma unroll
    for (int h = 0; h < NHEADS; h++) {
        float* q = base + h * HDIM;
        float q1 = q[0], q2 = q[64];
        q[0]  = q1 * c - q2 * s;
        q[64] = q2 * c + q1 * s;
        float* k = q + INNERD;
        float k1 = k[0], k2 = k[64];
        k[0]  = k1 * c - k2 * s;
        k[64] = k2 * c + k1 * s;
    }
}

// ---------------- Windowed flash attention (fp32, f32x2 packed) -------------
#define ATTN_SMEM_BYTES (3 * 64 * 132 * 4 + 64 * 76 * 4)

__global__ __launch_bounds__(256, 1) void attn_kernel() {
    extern __shared__ float sm[];
    float* sQ = sm;
    float* sK = sm + 64 * 132;
    float* sV = sm + 2 * 64 * 132;
    float* sP = sm + 3 * 64 * 132;

    int tid = threadIdx.x;
    int tx  = tid & 15;
    int ty  = tid >> 4;
    int qb  = blockIdx.x;
    int h   = blockIdx.y;
    int b   = blockIdx.z;
    int qs  = qb * 64;

    const float scale = 0.088388347648318447f;
    const float* qg = g_qkv + (long)(b * NSEQ + qs) * EQKV + h * HDIM;

    #pragma unroll
    for (int it = 0; it < 8; it++) {
        int e  = tid + it * 256;
        int rr = e >> 5;
        int c4 = (e & 31) << 2;
        float4 v = *(const float4*)(qg + (long)rr * EQKV + c4);
        v.x *= scale; v.y *= scale; v.z *= scale; v.w *= scale;
        *(float4*)&sQ[rr * 132 + c4] = v;
    }

    float mrow[4], lrow[4];
    ull oacc[4][4];
    #pragma unroll
    for (int i = 0; i < 4; i++) {
        mrow[i] = -1e30f; lrow[i] = 0.f;
        #pragma unroll
        for (int j = 0; j < 4; j++) oacc[i][j] = 0ULL;
    }

    int kt0 = (qs >= WINDOW) ? ((qs - WINDOW + 1) >> 6) : 0;
    int kt1 = qb;

    for (int kt = kt0; kt <= kt1; kt++) {
        int ks = kt << 6;
        __syncthreads();
        const float* kg = g_qkv + (long)(b * NSEQ + ks) * EQKV + INNERD + h * HDIM;
        const float* vg = kg + INNERD;
        #pragma unroll
        for (int it = 0; it < 8; it++) {
            int e  = tid + it * 256;
            int rr = e >> 5;
            int c4 = (e & 31) << 2;
            *(float4*)&sK[rr * 132 + c4] = *(const float4*)(kg + (long)rr * EQKV + c4);
            *(float4*)&sV[rr * 132 + c4] = *(const float4*)(vg + (long)rr * EQKV + c4);
        }
        __syncthreads();

        ull sacc[4][4];
        #pragma unroll
        for (int i = 0; i < 4; i++)
            #pragma unroll
            for (int j = 0; j < 4; j++) sacc[i][j] = 0ULL;

        #pragma unroll 8
        for (int d0 = 0; d0 < 128; d0 += 4) {
            ulonglong2 qv[4], kv[4];
            #pragma unroll
            for (int i = 0; i < 4; i++)
                qv[i] = *(const ulonglong2*)&sQ[(ty + 16 * i) * 132 + d0];
            #pragma unroll
            for (int j = 0; j < 4; j++)
                kv[j] = *(const ulonglong2*)&sK[(tx + 16 * j) * 132 + d0];
            #pragma unroll
            for (int i = 0; i < 4; i++)
                #pragma unroll
                for (int j = 0; j < 4; j++) {
                    ffma2(sacc[i][j], qv[i].x, kv[j].x);
                    ffma2(sacc[i][j], qv[i].y, kv[j].y);
                }
        }

        float s[4][4];
        #pragma unroll
        for (int i = 0; i < 4; i++)
            #pragma unroll
            for (int j = 0; j < 4; j++) s[i][j] = hadd2(sacc[i][j]);

        #pragma unroll
        for (int i = 0; i < 4; i++) {
            int qi = qs + ty + 16 * i;
            #pragma unroll
            for (int j = 0; j < 4; j++) {
                int kj = ks + tx + 16 * j;
                if (kj > qi || kj <= qi - WINDOW) s[i][j] = -1e30f;
            }
        }

        #pragma unroll
        for (int i = 0; i < 4; i++) {
            float mx = fmaxf(fmaxf(s[i][0], s[i][1]), fmaxf(s[i][2], s[i][3]));
            #pragma unroll
            for (int o = 1; o < 16; o <<= 1)
                mx = fmaxf(mx, __shfl_xor_sync(0xffffffffu, mx, o));
            float mnew  = fmaxf(mrow[i], mx);
            float alpha = __expf(mrow[i] - mnew);
            mrow[i] = mnew;

            float p[4], rs = 0.f;
            #pragma unroll
            for (int j = 0; j < 4; j++) {
                p[j] = (s[i][j] < -1e29f) ? 0.f : __expf(s[i][j] - mnew);
                rs += p[j];
            }
            #pragma unroll
            for (int o = 1; o < 16; o <<= 1)
                rs += __shfl_xor_sync(0xffffffffu, rs, o);
            lrow[i] = lrow[i] * alpha + rs;

            ull a2 = f2dup(alpha);
            #pragma unroll
            for (int j = 0; j < 4; j++) fmul2(oacc[i][j], a2);
            #pragma unroll
            for (int j = 0; j < 4; j++)
                sP[(ty + 16 * i) * 76 + tx + 16 * j] = p[j];
        }
        __syncthreads();

        #pragma unroll 8
        for (int j = 0; j < 64; j++) {
            const ull* vp = (const ull*)&sV[j * 132 + tx * 8];
            ull v0 = vp[0], v1 = vp[1], v2 = vp[2], v3 = vp[3];
            #pragma unroll
            for (int i = 0; i < 4; i++) {
                ull pd = f2dup(sP[(ty + 16 * i) * 76 + j]);
                ffma2(oacc[i][0], pd, v0);
                ffma2(oacc[i][1], pd, v1);
                ffma2(oacc[i][2], pd, v2);
                ffma2(oacc[i][3], pd, v3);
            }
        }
    }

    #pragma unroll
    for (int i = 0; i < 4; i++) {
        float inv = 1.0f / lrow[i];
        float4 c0, c1;
        c0.x = lo2(oacc[i][0]) * inv; c0.y = hi2(oacc[i][0]) * inv;
        c0.z = lo2(oacc[i][1]) * inv; c0.w = hi2(oacc[i][1]) * inv;
        c1.x = lo2(oacc[i][2]) * inv; c1.y = hi2(oacc[i][2]) * inv;
        c1.z = lo2(oacc[i][3]) * inv; c1.w = hi2(oacc[i][3]) * inv;
        float* op = g_att + (long)(b * NSEQ + qs + ty + 16 * i) * INNERD
                  + h * HDIM + tx * 8;
        *(float4*)op       = c0;
        *(float4*)(op + 4) = c1;
    }
}

// ---------------- launch ----------------
extern "C" void kernel_launch(void* const* d_in, const int* in_sizes, int n_in,
                              void* d_out, int out_size) {
    const float* x     = (const float*)d_in[0];
    const float* w_qkv = (const float*)d_in[1];
    const float* w_o   = (const float*)d_in[2];
    float* y = (float*)d_out;

    float *qkv = nullptr, *att = nullptr;
    __half *xh, *xl, *wq, *wo, *ah, *al;
    cudaGetSymbolAddress((void**)&qkv, g_qkv);
    cudaGetSymbolAddress((void**)&att, g_att);
    cudaGetSymbolAddress((void**)&xh,  g_xh);
    cudaGetSymbolAddress((void**)&xl,  g_xl);
    cudaGetSymbolAddress((void**)&wq,  g_wq);
    cudaGetSymbolAddress((void**)&wo,  g_wo);
    cudaGetSymbolAddress((void**)&ah,  g_ah);
    cudaGetSymbolAddress((void**)&al,  g_al);

    cudaFuncSetAttribute(gemm_tc,
                         cudaFuncAttributeMaxDynamicSharedMemorySize,
                         GEMM_SMEM_BYTES);
    cudaFuncSetAttribute(attn_kernel,
                         cudaFuncAttributeMaxDynamicSharedMemorySize,
                         ATTN_SMEM_BYTES);

    // 1) prepare fp16 operands
    {
        int n4 = (N_TOK * DMODEL) / 4;
        split_f16<<<n4 / 256, 256>>>((const float4*)x,
                                     (__half2*)xh, (__half2*)xl, n4);
    }
    {
        int n4 = (EQKV * DMODEL) / 4;
        conv_f16<<<n4 / 256, 256>>>((const float4*)w_qkv, (__half2*)wq, n4);
    }
    {
        int n4 = (DMODEL * INNERD) / 4;
        conv_f16<<<n4 / 256, 256>>>((const float4*)w_o, (__half2*)wo, n4);
    }

    // 2) QKV projection: [4096,2048] x [6144,2048]^T -> g_qkv [4096,6144]
    gemm_tc<<<dim3(EQKV / 128, N_TOK / 128), 256, GEMM_SMEM_BYTES>>>(
        xh, xl, wq, qkv, EQKV, DMODEL);

    // 3) RoPE in place on q,k
    rope_kernel<<<(N_TOK * 64) / 256, 256>>>();

    // 4) windowed attention -> g_att [4096, 2048]
    attn_kernel<<<dim3(NSEQ / 64, NHEADS, BATCH), 256, ATTN_SMEM_BYTES>>>();

    // 5) split attention output
    {
        int n4 = (N_TOK * INNERD) / 4;
        split_f16<<<n4 / 256, 256>>>((const float4*)att,
                                     (__half2*)ah, (__half2*)al, n4);
    }

    // 6) output projection: [4096,2048] x [2048,2048]^T -> y
    gemm_tc<<<dim3(DMODEL / 128, N_TOK / 128), 256, GEMM_SMEM_BYTES>>>(
        ah, al, wo, y, DMODEL, INNERD);
}

// round 9
// speedup vs baseline: 2.7422x; 1.2407x over previous
#include <cuda_runtime.h>
#include <cuda_fp16.h>
#include <cstdint>

#define BATCH   2
#define NSEQ    2048
#define DMODEL  2048
#define INNERD  2048
#define EQKV    6144
#define NHEADS  16
#define HDIM    128
#define WINDOW  512
#define N_TOK   (BATCH * NSEQ)   // 4096
#define NHTOT   (BATCH * NHEADS * NSEQ * HDIM)   // 8.4M

typedef unsigned long long ull;

// ---------------- scratch (__device__ globals) ----------------
__device__ float g_qkv[N_TOK * EQKV];                    // fp32 qkv
__device__ __align__(16) __half g_xh[N_TOK * DMODEL];    // x hi
__device__ __align__(16) __half g_xl[N_TOK * DMODEL];    // x lo
__device__ __align__(16) __half g_wq[EQKV * DMODEL];     // w_qkv rounded
__device__ __align__(16) __half g_wo[DMODEL * INNERD];   // w_o rounded
__device__ __align__(16) __half g_ah[N_TOK * INNERD];    // attn out hi
__device__ __align__(16) __half g_al[N_TOK * INNERD];    // attn out lo
// head-major roped q/k/v, fp16 hi/lo:
__device__ __align__(16) __half g_qh[NHTOT];
__device__ __align__(16) __half g_ql[NHTOT];
__device__ __align__(16) __half g_kh[NHTOT];
__device__ __align__(16) __half g_kl[NHTOT];
__device__ __align__(16) __half g_vh[NHTOT];
__device__ __align__(16) __half g_vl[NHTOT];

// ---------------- PTX helpers (baseline ISA only) ----------------
__device__ __forceinline__ uint32_t smem_u32(const void* p) {
    uint32_t a;
    asm("{ .reg .u64 t; cvta.to.shared.u64 t, %1; cvt.u32.u64 %0, t; }"
        : "=r"(a) : "l"(p));
    return a;
}
__device__ __forceinline__ void cp16(uint32_t dst, const void* src) {
    asm volatile("cp.async.cg.shared.global [%0], [%1], 16;" :: "r"(dst), "l"(src));
}
__device__ __forceinline__ void cp_commit() {
    asm volatile("cp.async.commit_group;" ::: "memory");
}
__device__ __forceinline__ void ldsm_x4(uint32_t* r, uint32_t addr) {
    asm volatile("ldmatrix.sync.aligned.m8n8.x4.shared.b16 {%0,%1,%2,%3}, [%4];"
                 : "=r"(r[0]), "=r"(r[1]), "=r"(r[2]), "=r"(r[3]) : "r"(addr));
}
__device__ __forceinline__ void ldsm_x2(uint32_t* r, uint32_t addr) {
    asm volatile("ldmatrix.sync.aligned.m8n8.x2.shared.b16 {%0,%1}, [%2];"
                 : "=r"(r[0]), "=r"(r[1]) : "r"(addr));
}
__device__ __forceinline__ void ldsm_x4t(uint32_t* r, uint32_t addr) {
    asm volatile("ldmatrix.sync.aligned.m8n8.x4.trans.shared.b16 {%0,%1,%2,%3}, [%4];"
                 : "=r"(r[0]), "=r"(r[1]), "=r"(r[2]), "=r"(r[3]) : "r"(addr));
}
__device__ __forceinline__ void mma16816(float* c, const uint32_t* a, const uint32_t* b) {
    asm volatile("mma.sync.aligned.m16n8k16.row.col.f32.f16.f16.f32 "
                 "{%0,%1,%2,%3}, {%4,%5,%6,%7}, {%8,%9}, {%0,%1,%2,%3};"
                 : "+f"(c[0]), "+f"(c[1]), "+f"(c[2]), "+f"(c[3])
                 : "r"(a[0]), "r"(a[1]), "r"(a[2]), "r"(a[3]),
                   "r"(b[0]), "r"(b[1]));
}
__device__ __forceinline__ void splith(float x, __half& h, __half& l) {
    h = __float2half_rn(x);
    l = __float2half_rn(x - __half2float(h));
}
__device__ __forceinline__ uint32_t pack2(__half a, __half b) {
    __half2 t = __halves2half2(a, b);
    return *(uint32_t*)&t;
}

// ---------------- fp32 -> fp16 hi/lo split (activations) ----------------
__global__ void split_f16(const float4* __restrict__ in,
                          __half2* __restrict__ hi,
                          __half2* __restrict__ lo, int n4) {
    int i = blockIdx.x * blockDim.x + threadIdx.x;
    if (i >= n4) return;
    float4 v = in[i];
    __half h0, l0, h1, l1, h2, l2, h3, l3;
    splith(v.x, h0, l0); splith(v.y, h1, l1);
    splith(v.z, h2, l2); splith(v.w, h3, l3);
    hi[i * 2]     = __halves2half2(h0, h1);
    hi[i * 2 + 1] = __halves2half2(h2, h3);
    lo[i * 2]     = __halves2half2(l0, l1);
    lo[i * 2 + 1] = __halves2half2(l2, l3);
}

// ---------------- fp32 -> fp16 round (weights) ----------------
__global__ void conv_f16(const float4* __restrict__ in,
                         __half2* __restrict__ out, int n4) {
    int i = blockIdx.x * blockDim.x + threadIdx.x;
    if (i >= n4) return;
    float4 v = in[i];
    out[i * 2]     = __halves2half2(__float2half_rn(v.x), __float2half_rn(v.y));
    out[i * 2 + 1] = __halves2half2(__float2half_rn(v.z), __float2half_rn(v.w));
}

// ---------------- mma.sync split-fp16 NT GEMM (unchanged from R7) ----------
#define GEMM_STAGE   24576
#define GEMM_NSTAGE  3
#define GEMM_SMEM_BYTES (GEMM_NSTAGE * GEMM_STAGE)

__device__ __forceinline__ void load_stage_body(
    uint32_t st, const __half* __restrict__ Ah, const __half* __restrict__ Al,
    const __half* __restrict__ Bw, long tm, long tn, int k0, int K, int tid)
{
    #pragma unroll
    for (int it = 0; it < 6; it++) {
        int s = tid + it * 256;
        uint32_t dst; const __half* src; long row;
        if (s < 1024) {
            int hl = s >> 9;
            int r  = (s >> 2) & 127;
            int q  = s & 3;
            src = hl ? Al : Ah; row = tm + r;
            dst = st + hl * 8192 + (q >> 1) * 4096 + r * 32 + (q & 1) * 16;
            cp16(dst, src + row * (long)K + k0 + q * 8);
        } else {
            int s2 = s - 1024;
            int r  = (s2 >> 2) & 127;
            int q  = s2 & 3;
            row = tn + r;
            dst = st + 16384 + (q >> 1) * 4096 + r * 32 + (q & 1) * 16;
            cp16(dst, Bw + row * (long)K + k0 + q * 8);
        }
    }
}

__global__ __launch_bounds__(256, 2) void gemm_tc(
    const __half* __restrict__ Ah, const __half* __restrict__ Al,
    const __half* __restrict__ Bw,
    float* __restrict__ C, int Nn, int K)
{
    extern __shared__ char dynsmem[];
    uint32_t st0 = smem_u32(dynsmem);

    int tid  = threadIdx.x;
    int lane = tid & 31;
    int wid  = tid >> 5;
    int wm   = (wid >> 2) * 64;
    int wn   = (wid & 3) * 32;

    long tm = (long)blockIdx.y * 128;
    long tn = (long)blockIdx.x * 128;
    int NC = K / 32;

    uint32_t aOff = (uint32_t)((wm + (lane & 15)) * 32 + (lane >> 4) * 16);
    uint32_t bOff = (uint32_t)((wn + (lane & 7)) * 32 + ((lane >> 3) & 1) * 16);

    float acc[4][4][4];
    #pragma unroll
    for (int mi = 0; mi < 4; mi++)
        #pragma unroll
        for (int ni = 0; ni < 4; ni++)
            #pragma unroll
            for (int q = 0; q < 4; q++) acc[mi][ni][q] = 0.f;

    load_stage_body(st0, Ah, Al, Bw, tm, tn, 0, K, tid);
    cp_commit();
    if (NC > 1) load_stage_body(st0 + GEMM_STAGE, Ah, Al, Bw, tm, tn, 32, K, tid);
    cp_commit();

    int stg = 0, stg2 = 2;
    for (int c = 0; c < NC; c++) {
        asm volatile("cp.async.wait_group 1;" ::: "memory");
        __syncthreads();

        if (c + 2 < NC)
            load_stage_body(st0 + stg2 * GEMM_STAGE, Ah, Al, Bw,
                            tm, tn, (c + 2) * 32, K, tid);
        cp_commit();

        uint32_t sa = st0 + stg * GEMM_STAGE;
        uint32_t sb = sa + 16384;

        #pragma unroll
        for (int kc = 0; kc < 2; kc++) {
            uint32_t ab = sa + kc * 4096 + aOff;
            uint32_t bb = sb + kc * 4096 + bOff;

            uint32_t aH[4][4], aL[4][4], bH[4][2];
            #pragma unroll
            for (int mi = 0; mi < 4; mi++) {
                ldsm_x4(aH[mi], ab + mi * 512);
                ldsm_x4(aL[mi], ab + 8192 + mi * 512);
            }
            #pragma unroll
            for (int ni = 0; ni < 4; ni++)
                ldsm_x2(bH[ni], bb + ni * 256);

            #pragma unroll
            for (int mi = 0; mi < 4; mi++)
                #pragma unroll
                for (int ni = 0; ni < 4; ni++) {
                    mma16816(acc[mi][ni], aH[mi], bH[ni]);
                    mma16816(acc[mi][ni], aL[mi], bH[ni]);
                }
        }

        stg  = (stg  + 1 == GEMM_NSTAGE) ? 0 : stg + 1;
        stg2 = (stg2 + 1 == GEMM_NSTAGE) ? 0 : stg2 + 1;
    }

    int r0 = (lane >> 2);
    int c0 = (lane & 3) * 2;
    #pragma unroll
    for (int mi = 0; mi < 4; mi++) {
        long row = tm + wm + mi * 16 + r0;
        #pragma unroll
        for (int ni = 0; ni < 4; ni++) {
            long col = tn + wn + ni * 8 + c0;
            *(float2*)&C[row * (long)Nn + col] =
                make_float2(acc[mi][ni][0], acc[mi][ni][1]);
            *(float2*)&C[(row + 8) * (long)Nn + col] =
                make_float2(acc[mi][ni][2], acc[mi][ni][3]);
        }
    }
}

// ---------------- RoPE + head-major fp16 hi/lo split ----------------
// thread per (token m, pair d<64); loops over heads.
// writes q (scaled), k, v to [B][H][N][128] hi/lo arrays.
__global__ void rope_split() {
    int idx = blockIdx.x * blockDim.x + threadIdx.x;
    if (idx >= N_TOK * 64) return;
    int d = idx & 63;
    int m = idx >> 6;
    int n = m & (NSEQ - 1);
    int b = m >> 11;

    double inv = exp(-(double)d * (9.210340371976184 / 64.0));
    double ang = (double)n * inv;
    const double TWO_PI = 6.283185307179586476925286766559;
    double w = ang - floor(ang / TWO_PI) * TWO_PI;
    float c = cosf((float)w);
    float s = sinf((float)w);
    const float scale = 0.088388347648318447f;   // 1/sqrt(128)

    const float* base = g_qkv + (long)m * EQKV;
    #pragma unroll
    for (int h = 0; h < NHEADS; h++) {
        const float* q = base + h * HDIM;
        const float* k = q + INNERD;
        const float* v = k + INNERD;
        float q1 = q[d], q2 = q[d + 64];
        float k1 = k[d], k2 = k[d + 64];
        float v1 = v[d], v2 = v[d + 64];
        float qr1 = (q1 * c - q2 * s) * scale;
        float qr2 = (q2 * c + q1 * s) * scale;
        float kr1 = k1 * c - k2 * s;
        float kr2 = k2 * c + k1 * s;

        long o = ((long)(b * NHEADS + h) * NSEQ + n) * HDIM;
        __half hh, ll;
        splith(qr1, hh, ll); g_qh[o + d] = hh;      g_ql[o + d] = ll;
        splith(qr2, hh, ll); g_qh[o + d + 64] = hh; g_ql[o + d + 64] = ll;
        splith(kr1, hh, ll); g_kh[o + d] = hh;      g_kl[o + d] = ll;
        splith(kr2, hh, ll); g_kh[o + d + 64] = hh; g_kl[o + d + 64] = ll;
        splith(v1,  hh, ll); g_vh[o + d] = hh;      g_vl[o + d] = ll;
        splith(v2,  hh, ll); g_vh[o + d + 64] = hh; g_vl[o + d + 64] = ll;
    }
}

// ---------------- HMMA flash attention ----------------
// CTA = 128 queries x (head, batch). 256 threads, 8 warps; warp owns 16 rows.
// SMEM (chunked layout: [k16-chunk][row][32B], conflict-free ldsm):
//   sQh, sQl: 8 chunks x 128 rows x 32B = 32KB each
//   per KV stage: kh,kl,vh,vl each 8 x 64 x 32 = 16KB -> 64KB; 2 stages.
#define AQ 128
#define SQ_BYTES 32768
#define SK_BYTES 16384
#define ASTAGE   (4 * SK_BYTES)                     // 64KB
#define ATTN_SMEM_BYTES (2 * SQ_BYTES + 2 * ASTAGE) // 192KB

__device__ __forceinline__ void load_q(uint32_t sQh, uint32_t sQl,
                                       const __half* qh, const __half* ql, int tid) {
    #pragma unroll
    for (int it = 0; it < 16; it++) {
        int s = tid + it * 256;          // 0..4095
        int mat = s >> 11;               // 0=hi, 1=lo
        int r = (s >> 4) & 127;
        int q = s & 15;
        uint32_t dst = (mat ? sQl : sQh) + (q >> 1) * 4096 + r * 32 + (q & 1) * 16;
        cp16(dst, (mat ? ql : qh) + r * 128 + q * 8);
    }
}

__device__ __forceinline__ void load_kv(uint32_t st,
                                        const __half* kh, const __half* kl,
                                        const __half* vh, const __half* vl, int tid) {
    #pragma unroll
    for (int it = 0; it < 16; it++) {
        int s = tid + it * 256;          // 0..4095
        int mat = s >> 10;               // 0..3
        int r = (s >> 4) & 63;
        int q = s & 15;
        const __half* src = (mat == 0) ? kh : (mat == 1) ? kl : (mat == 2) ? vh : vl;
        uint32_t dst = st + mat * SK_BYTES + (q >> 1) * 2048 + r * 32 + (q & 1) * 16;
        cp16(dst, src + r * 128 + q * 8);
    }
}

__global__ __launch_bounds__(256, 1) void attn_tc() {
    extern __shared__ char dynsmem[];
    uint32_t sb  = smem_u32(dynsmem);
    uint32_t sQh = sb;
    uint32_t sQl = sb + SQ_BYTES;
    uint32_t st0 = sb + 2 * SQ_BYTES;

    int tid  = threadIdx.x;
    int lane = tid & 31;
    int wid  = tid >> 5;
    int qb   = blockIdx.x;
    int h    = blockIdx.y;
    int b    = blockIdx.z;
    int qs   = qb * AQ;

    long hb = (long)(b * NHEADS + h) * NSEQ;
    const __half* qhg = g_qh + (hb + qs) * HDIM;
    const __half* qlg = g_ql + (hb + qs) * HDIM;

    int kt0 = (qs >= WINDOW) ? ((qs - WINDOW + 1) >> 6) : 0;
    int kt1 = (qs + AQ - 1) >> 6;

    // prologue loads: group0 = Q + tile kt0; group1 = tile kt0+1
    load_q(sQh, sQl, qhg, qlg, tid);
    {
        int ks = kt0 * 64;
        load_kv(st0, g_kh + (hb + ks) * HDIM, g_kl + (hb + ks) * HDIM,
                g_vh + (hb + ks) * HDIM, g_vl + (hb + ks) * HDIM, tid);
    }
    cp_commit();
    if (kt0 + 1 <= kt1) {
        int ks = (kt0 + 1) * 64;
        load_kv(st0 + ASTAGE, g_kh + (hb + ks) * HDIM, g_kl + (hb + ks) * HDIM,
                g_vh + (hb + ks) * HDIM, g_vl + (hb + ks) * HDIM, tid);
    }
    cp_commit();

    int qw = qs + wid * 16;              // warp's first global q row
    int r0 = lane >> 2;
    int cb = (lane & 3) * 2;

    // per-lane ldsm offsets (same patterns as gemm_tc, verified)
    uint32_t qOff = (uint32_t)((wid * 16 + (lane & 15)) * 32 + (lane >> 4) * 16);
    uint32_t kRow = (uint32_t)((lane & 7) + ((lane >> 4) << 3));   // + 16*pair later
    uint32_t kHlf = (uint32_t)(((lane >> 3) & 1) * 16);
    uint32_t vOff = (uint32_t)((lane & 15) * 32 + (lane >> 4) * 16);  // + t*512 + cc*2048

    float mrow[2], lrow[2];
    float oacc[16][4];
    mrow[0] = mrow[1] = -1e30f;
    lrow[0] = lrow[1] = 0.f;
    #pragma unroll
    for (int nt = 0; nt < 16; nt++)
        #pragma unroll
        for (int q = 0; q < 4; q++) oacc[nt][q] = 0.f;

    for (int kt = kt0; kt <= kt1; kt++) {
        int st = (kt - kt0) & 1;
        asm volatile("cp.async.wait_group 1;" ::: "memory");
        __syncthreads();

        int ks = kt * 64;
        uint32_t S  = st0 + st * ASTAGE;
        uint32_t kh_ = S, kl_ = S + SK_BYTES;
        uint32_t vh_ = S + 2 * SK_BYTES, vl_ = S + 3 * SK_BYTES;

        // warp-level tile skip: any (qi in [qw, qw+15], kj in tile) valid?
        bool active = (ks <= qw + 15) && (ks + 63 > qw - WINDOW);

        if (active) {
            // ---- S = Q K^T ----
            float sacc[8][4];
            #pragma unroll
            for (int nt = 0; nt < 8; nt++)
                #pragma unroll
                for (int q = 0; q < 4; q++) sacc[nt][q] = 0.f;

            #pragma unroll
            for (int c = 0; c < 8; c++) {
                uint32_t aH[4], aL[4];
                ldsm_x4(aH, sQh + c * 4096 + qOff);
                ldsm_x4(aL, sQl + c * 4096 + qOff);
                #pragma unroll
                for (int p = 0; p < 4; p++) {   // n-tile pairs {2p, 2p+1}
                    uint32_t addr = (p * 16 + kRow) * 32 + kHlf + c * 2048;
                    uint32_t bh[4], bl[4];
                    ldsm_x4(bh, kh_ + addr);
                    ldsm_x4(bl, kl_ + addr);
                    mma16816(sacc[2 * p],     aH, bh);
                    mma16816(sacc[2 * p],     aH, bl);
                    mma16816(sacc[2 * p],     aL, bh);
                    mma16816(sacc[2 * p + 1], aH, bh + 2);
                    mma16816(sacc[2 * p + 1], aH, bl + 2);
                    mma16816(sacc[2 * p + 1], aL, bh + 2);
                }
            }

            // ---- mask + online softmax (warp-local rows) ----
            #pragma unroll
            for (int hf = 0; hf < 2; hf++) {
                int qi = qw + r0 + hf * 8;
                float mx = -1e30f;
                #pragma unroll
                for (int nt = 0; nt < 8; nt++) {
                    int kj0 = ks + nt * 8 + cb;
                    float v0 = sacc[nt][hf * 2], v1 = sacc[nt][hf * 2 + 1];
                    if (kj0 > qi || kj0 <= qi - WINDOW) v0 = -1e30f;
                    if (kj0 + 1 > qi || kj0 + 1 <= qi - WINDOW) v1 = -1e30f;
                    sacc[nt][hf * 2] = v0; sacc[nt][hf * 2 + 1] = v1;
                    mx = fmaxf(mx, fmaxf(v0, v1));
                }
                mx = fmaxf(mx, __shfl_xor_sync(0xffffffffu, mx, 1));
                mx = fmaxf(mx, __shfl_xor_sync(0xffffffffu, mx, 2));
                float mnew  = fmaxf(mrow[hf], mx);
                float alpha = __expf(mrow[hf] - mnew);
                mrow[hf] = mnew;

                float rs = 0.f;
                #pragma unroll
                for (int nt = 0; nt < 8; nt++) {
                    float v0 = sacc[nt][hf * 2], v1 = sacc[nt][hf * 2 + 1];
                    float p0 = (v0 < -1e29f) ? 0.f : __expf(v0 - mnew);
                    float p1 = (v1 < -1e29f) ? 0.f : __expf(v1 - mnew);
                    sacc[nt][hf * 2] = p0; sacc[nt][hf * 2 + 1] = p1;
                    rs += p0 + p1;
                }
                rs += __shfl_xor_sync(0xffffffffu, rs, 1);
                rs += __shfl_xor_sync(0xffffffffu, rs, 2);
                lrow[hf] = lrow[hf] * alpha + rs;

                #pragma unroll
                for (int nt = 0; nt < 16; nt++) {
                    oacc[nt][hf * 2]     *= alpha;
                    oacc[nt][hf * 2 + 1] *= alpha;
                }
            }

            // ---- P -> fp16 hi/lo a-fragments ----
            uint32_t aPh[4][4], aPl[4][4];
            #pragma unroll
            for (int t = 0; t < 4; t++) {
                #pragma unroll
                for (int j = 0; j < 4; j++) {
                    int nt = 2 * t + (j >> 1);
                    int q0 = (j & 1) * 2;
                    __half h0, l0, h1, l1;
                    splith(sacc[nt][q0],     h0, l0);
                    splith(sacc[nt][q0 + 1], h1, l1);
                    aPh[t][j] = pack2(h0, h1);
                    aPl[t][j] = pack2(l0, l1);
                }
            }

            // ---- O += P V ----
            #pragma unroll
            for (int t = 0; t < 4; t++) {
                #pragma unroll
                for (int cc = 0; cc < 8; cc++) {
                    uint32_t addr = cc * 2048 + t * 512 + vOff;
                    uint32_t vh[4], vl[4];
                    ldsm_x4t(vh, vh_ + addr);
                    ldsm_x4t(vl, vl_ + addr);
                    mma16816(oacc[2 * cc],     aPh[t], vh);
                    mma16816(oacc[2 * cc],     aPh[t], vl);
                    mma16816(oacc[2 * cc],     aPl[t], vh);
                    mma16816(oacc[2 * cc + 1], aPh[t], vh + 2);
                    mma16816(oacc[2 * cc + 1], aPh[t], vl + 2);
                    mma16816(oacc[2 * cc + 1], aPl[t], vh + 2);
                }
            }
        }

        __syncthreads();
        // prefetch tile kt+2 into the stage just consumed
        if (kt + 2 <= kt1) {
            int ks2 = (kt + 2) * 64;
            load_kv(st0 + st * ASTAGE,
                    g_kh + (hb + ks2) * HDIM, g_kl + (hb + ks2) * HDIM,
                    g_vh + (hb + ks2) * HDIM, g_vl + (hb + ks2) * HDIM, tid);
        }
        cp_commit();
    }

    // ---- epilogue: normalize, split to fp16 hi/lo at [tok][h*128+d] ----
    #pragma unroll
    for (int hf = 0; hf < 2; hf++) {
        float inv = 1.0f / lrow[hf];
        long tok = (long)b * NSEQ + qw + r0 + hf * 8;
        #pragma unroll
        for (int nt = 0; nt < 16; nt++) {
            int col = h * HDIM + nt * 8 + cb;
            float o0 = oacc[nt][hf * 2] * inv;
            float o1 = oacc[nt][hf * 2 + 1] * inv;
            __half h0, l0, h1, l1;
            splith(o0, h0, l0);
            splith(o1, h1, l1);
            *(__half2*)&g_ah[tok * INNERD + col] = __halves2half2(h0, h1);
            *(__half2*)&g_al[tok * INNERD + col] = __halves2half2(l0, l1);
        }
    }
}

// ---------------- launch ----------------
extern "C" void kernel_launch(void* const* d_in, const int* in_sizes, int n_in,
                              void* d_out, int out_size) {
    const float* x     = (const float*)d_in[0];
    const float* w_qkv = (const float*)d_in[1];
    const float* w_o   = (const float*)d_in[2];
    float* y = (float*)d_out;

    float* qkv = nullptr;
    __half *xh, *xl, *wq, *wo, *ah, *al;
    cudaGetSymbolAddress((void**)&qkv, g_qkv);
    cudaGetSymbolAddress((void**)&xh,  g_xh);
    cudaGetSymbolAddress((void**)&xl,  g_xl);
    cudaGetSymbolAddress((void**)&wq,  g_wq);
    cudaGetSymbolAddress((void**)&wo,  g_wo);
    cudaGetSymbolAddress((void**)&ah,  g_ah);
    cudaGetSymbolAddress((void**)&al,  g_al);

    cudaFuncSetAttribute(gemm_tc,
                         cudaFuncAttributeMaxDynamicSharedMemorySize,
                         GEMM_SMEM_BYTES);
    cudaFuncSetAttribute(attn_tc,
                         cudaFuncAttributeMaxDynamicSharedMemorySize,
                         ATTN_SMEM_BYTES);

    // 1) prepare fp16 operands for QKV projection
    {
        int n4 = (N_TOK * DMODEL) / 4;
        split_f16<<<n4 / 256, 256>>>((const float4*)x,
                                     (__half2*)xh, (__half2*)xl, n4);
    }
    {
        int n4 = (EQKV * DMODEL) / 4;
        conv_f16<<<n4 / 256, 256>>>((const float4*)w_qkv, (__half2*)wq, n4);
    }
    {
        int n4 = (DMODEL * INNERD) / 4;
        conv_f16<<<n4 / 256, 256>>>((const float4*)w_o, (__half2*)wo, n4);
    }

    // 2) QKV projection -> g_qkv fp32
    gemm_tc<<<dim3(EQKV / 128, N_TOK / 128), 256, GEMM_SMEM_BYTES>>>(
        xh, xl, wq, qkv, EQKV, DMODEL);

    // 3) RoPE + head-major fp16 hi/lo split
    rope_split<<<(N_TOK * 64) / 256, 256>>>();

    // 4) HMMA flash attention -> g_ah/g_al (fp16 hi/lo, [tok][inner])
    attn_tc<<<dim3(NSEQ / AQ, NHEADS, BATCH), 256, ATTN_SMEM_BYTES>>>();

    // 5) output projection -> y
    gemm_tc<<<dim3(DMODEL / 128, N_TOK / 128), 256, GEMM_SMEM_BYTES>>>(
        ah, al, wo, y, DMODEL, INNERD);
}